// round 7
// baseline (speedup 1.0000x reference)
#include <cuda_runtime.h>
#include <cuda_fp16.h>
#include <cstdint>

#define DIM      4096
#define NPAIRS   2048
#define GRD      64
#define P_TILE   8                               // pairs staged per block
#define THREADS  1024
#define SLOTS    4                               // pair-slots (2 pairs each)
#define BSTEP    (THREADS / SLOTS)               // 256 batch rows per iteration
#define GRID_ELEMS (GRD * GRD)                   // 4096 cells per pair
#define GRID_SMEM  (P_TILE * GRID_ELEMS * 4)     // 128 KB (half2 dup-pair cells)
#define DEPTH    4                               // x-ring stages
#define STAGE_BYTES (THREADS * 16)               // 16 KB per stage
#define RING_SMEM  (DEPTH * STAGE_BYTES)         // 64 KB
#define SMEM_BYTES (GRID_SMEM + RING_SMEM)       // 192 KB

__device__ __forceinline__ uint32_t smem_u32(const void* p) {
    return (uint32_t)__cvta_generic_to_shared(p);
}
__device__ __forceinline__ void cp_async16(uint32_t saddr, const void* gptr) {
    asm volatile("cp.async.cg.shared.global [%0], [%1], 16;\n"
                 :: "r"(saddr), "l"(gptr) : "memory");
}
__device__ __forceinline__ void cp_commit() {
    asm volatile("cp.async.commit_group;\n" ::: "memory");
}
__device__ __forceinline__ void cp_wait_all_but3() {
    asm volatile("cp.async.wait_group 3;\n" ::: "memory");
}

__global__ void __launch_bounds__(THREADS, 1)
pair_bilinear_kernel(const float* __restrict__ x,
                     const float* __restrict__ pairW,
                     const float* __restrict__ Y,
                     float* __restrict__ out,
                     int b_tile, int iters)
{
    extern __shared__ __half2 sY[];  // [P_TILE][64][64] dup-pair cells, then x ring
    char* ring = reinterpret_cast<char*>(sY) + GRID_SMEM;

    const int p0 = blockIdx.x * P_TILE;

    // ── Stage: duplicated-pair fp16 grid from fp32 Y, vectorized stores ──
    {
        const float4* __restrict__ Yg =
            reinterpret_cast<const float4*>(Y) + p0 * (GRID_ELEMS / 4);
        uint4* __restrict__ sY4 = reinterpret_cast<uint4*>(sY);
        #pragma unroll
        for (int i = threadIdx.x; i < P_TILE * GRID_ELEMS / 4; i += THREADS) {
            const float4 v = Yg[i];
            const int c4 = i & 15;               // float4 index within 64-wide row
            const float vnext = (c4 < 15) ? *reinterpret_cast<const float*>(Yg + i + 1)
                                          : v.w;  // cell 63 never read
            __half2 h[4];
            h[0] = __floats2half2_rn(v.x, v.y);
            h[1] = __floats2half2_rn(v.y, v.z);
            h[2] = __floats2half2_rn(v.z, v.w);
            h[3] = __floats2half2_rn(v.w, vnext);
            sY4[i] = *reinterpret_cast<const uint4*>(h);   // STS.128, conflict-free
        }
    }

    const int tid = threadIdx.x;
    const int sl  = tid & (SLOTS - 1);           // pair-slot (0..3) -> pairs 2sl,2sl+1
    const int bs  = tid >> 2;                    // batch sub-index (0..255)
    const int pA  = p0 + 2 * sl;                 // first pair of this thread

    const float4 wA = *(reinterpret_cast<const float4*>(pairW) + pA);
    const float4 wB = *(reinterpret_cast<const float4*>(pairW) + pA + 1);

    const __half2* __restrict__ sA = sY + (2 * sl) * GRID_ELEMS;
    const __half2* __restrict__ sB = sA + GRID_ELEMS;

    const int bstart = blockIdx.y * b_tile + bs;

    // gmem x source for stage s: row (bstart + s*BSTEP), float4 column (pA>>1)
    const float4* __restrict__ xg =
        reinterpret_cast<const float4*>(x) + (size_t)bstart * (DIM / 4) + (pA >> 1);
    const int XSTR = BSTEP * (DIM / 4);

    float2* __restrict__ op =
        reinterpret_cast<float2*>(out + (size_t)bstart * NPAIRS + pA);
    const int OSTR = BSTEP * (NPAIRS / 2);

    // my private ring slots (16B each)
    const uint32_t ring_base = smem_u32(ring) + tid * 16;

    // ── Prologue: prefetch stages 0..DEPTH-2, one commit group per stage ──
    #pragma unroll
    for (int d = 0; d < DEPTH - 1; d++) {
        cp_async16(ring_base + d * STAGE_BYTES, xg + (size_t)d * XSTR);
        cp_commit();
    }

    __syncthreads();   // grid staging complete (also after prologue issues)

    // ── Main loop: per-thread async pipeline, no block syncs ─────────────
    for (int k = 0; k < iters; ++k) {
        const int s_issue = k + DEPTH - 1;
        if (s_issue < iters)
            cp_async16(ring_base + (s_issue & (DEPTH - 1)) * STAGE_BYTES,
                       xg + (size_t)s_issue * XSTR);
        cp_commit();
        cp_wait_all_but3();                      // stage k is now resident

        const float4 xv = *reinterpret_cast<const float4*>(
            ring + (k & (DEPTH - 1)) * STAGE_BYTES + tid * 16);

        // pair A uses (xv.x, xv.y), pair B uses (xv.z, xv.w)
        const float a0 = fmaf(xv.x, wA.x, xv.y * wA.z);
        const float a1 = fmaf(xv.x, wA.y, xv.y * wA.w);
        const float b0 = fmaf(xv.z, wB.x, xv.w * wB.z);
        const float b1 = fmaf(xv.z, wB.y, xv.w * wB.w);

        const float gA0 = fminf(fmaxf(a0 * 63.0f, 0.0f), 63.0f);
        const float gA1 = fminf(fmaxf(a1 * 63.0f, 0.0f), 63.0f);
        const float gB0 = fminf(fmaxf(b0 * 63.0f, 0.0f), 63.0f);
        const float gB1 = fminf(fmaxf(b1 * 63.0f, 0.0f), 63.0f);

        const int rA = min((int)gA0, 62), cA = min((int)gA1, 62);
        const int rB = min((int)gB0, 62), cB = min((int)gB1, 62);
        const float frA = gA0 - (float)rA, fcA = gA1 - (float)cA;
        const float frB = gB0 - (float)rB, fcB = gB1 - (float)cB;

        const int baseA = (rA << 6) + cA;
        const int baseB = (rB << 6) + cB;
        const __half2 tA = sA[baseA], bA = sA[baseA + GRD];
        const __half2 tB = sB[baseB], bB = sB[baseB + GRD];

        const float2 ta = __half22float2(tA);
        const float2 ba = __half22float2(bA);
        const float2 tb = __half22float2(tB);
        const float2 bb = __half22float2(bB);

        const float topA = fmaf(fcA, ta.y - ta.x, ta.x);
        const float botA = fmaf(fcA, ba.y - ba.x, ba.x);
        const float topB = fmaf(fcB, tb.y - tb.x, tb.x);
        const float botB = fmaf(fcB, bb.y - bb.x, bb.x);

        float2 o;
        o.x = fmaf(frA, botA - topA, topA);
        o.y = fmaf(frB, botB - topB, topB);
        __stcs(op, o);                            // streaming store, keep Y in L2
        op += OSTR;
    }
}

extern "C" void kernel_launch(void* const* d_in, const int* in_sizes, int n_in,
                              void* d_out, int out_size)
{
    const float* x     = (const float*)d_in[0];
    const float* pairW = (const float*)d_in[1];
    const float* Y     = (const float*)d_in[2];
    float* out         = (float*)d_out;

    const int batch = in_sizes[0] / DIM;   // 8192

    const int b_blocks = 4;
    const int b_tile = batch / b_blocks;                 // 2048
    const int iters  = b_tile / BSTEP;                   // 8

    cudaFuncSetAttribute(pair_bilinear_kernel,
                         cudaFuncAttributeMaxDynamicSharedMemorySize, SMEM_BYTES);

    dim3 grid(NPAIRS / P_TILE, b_blocks);   // (256, 4) = 1024 blocks
    pair_bilinear_kernel<<<grid, THREADS, SMEM_BYTES>>>(x, pairW, Y, out, b_tile, iters);
}